// round 10
// baseline (speedup 1.0000x reference)
#include <cuda_runtime.h>
#include <stdint.h>

// TBE pooled embedding forward — 256-bit load experiment.
// weights: [T, E, D] fp32; indices: [T*B*L] int32; offsets: [T*B+1] int32
// out: [B, T*D] fp32, pooled bag (t, b) -> out[b, t*D : (t+1)*D]
//
// One warp per bag. Half-warp row split: lanes 0-15 handle even rows,
// lanes 16-31 odd rows; each lane loads 32B via ld.global.cg.v8.f32, so one
// LDG.256 warp instruction fetches TWO 512B rows. This doubles in-flight
// bytes per outstanding-LDG slot — the discriminating test between the
// "outstanding-request slot cap" and "wavefront-queue / DRAM service"
// explanations of the ~6 TB/s plateau.

#define T_TABLES 16
#define E_ROWS   100000
#define D_DIM    128
#define B_BAGS   4096

struct F8 { float f[8]; };

__device__ __forceinline__ F8 ldcg_f8(const float* p) {
    F8 v;
    asm volatile("ld.global.cg.v8.f32 {%0,%1,%2,%3,%4,%5,%6,%7}, [%8];"
                 : "=f"(v.f[0]), "=f"(v.f[1]), "=f"(v.f[2]), "=f"(v.f[3]),
                   "=f"(v.f[4]), "=f"(v.f[5]), "=f"(v.f[6]), "=f"(v.f[7])
                 : "l"(p));
    return v;
}

__device__ __forceinline__ float4 ldcg_f4(const float4* p) {
    float4 v;
    asm volatile("ld.global.cg.v4.f32 {%0,%1,%2,%3}, [%4];"
                 : "=f"(v.x), "=f"(v.y), "=f"(v.z), "=f"(v.w) : "l"(p));
    return v;
}

__device__ __forceinline__ void acc_add(float4& a, const float4 v) {
    a.x += v.x; a.y += v.y; a.z += v.z; a.w += v.w;
}

__global__ __launch_bounds__(256)
void tbe_forward_kernel(const float* __restrict__ weights,
                        const int* __restrict__ indices,
                        const int* __restrict__ offsets,
                        float* __restrict__ out) {
    const int warp_id = (blockIdx.x * blockDim.x + threadIdx.x) >> 5;
    const int lane    = threadIdx.x & 31;

    const int num_bags = T_TABLES * B_BAGS;
    if (warp_id >= num_bags) return;

    const int t = warp_id / B_BAGS;   // bags are table-major
    const int b = warp_id % B_BAGS;

    const int start = __ldg(offsets + warp_id);
    const int end   = __ldg(offsets + warp_id + 1);
    const int n     = end - start;

    const float* __restrict__ tblf = weights + (size_t)t * E_ROWS * D_DIM;

    if (n == 20 && ((start & 3) == 0)) {
        const int half    = lane >> 4;        // 0: even rows, 1: odd rows
        const int sublane = lane & 15;        // 32B slot within the row

        // Vectorized index fetch.
        const int4* __restrict__ ip = reinterpret_cast<const int4*>(indices + start);
        int idx[20];
        #pragma unroll
        for (int g = 0; g < 5; g++) {
            const int4 q = ip[g];
            idx[g * 4 + 0] = q.x;
            idx[g * 4 + 1] = q.y;
            idx[g * 4 + 2] = q.z;
            idx[g * 4 + 3] = q.w;
        }

        float acc[8] = {0.f, 0.f, 0.f, 0.f, 0.f, 0.f, 0.f, 0.f};

        // 10 row-pairs; this lane covers row 2j+half, bytes [sublane*32, +32).
        // Groups of 2 pairs to bound live registers (~16 temps).
        #pragma unroll
        for (int j = 0; j < 10; j += 2) {
            const int r0 = idx[2 * (j + 0) + half];
            const int r1 = idx[2 * (j + 1) + half];
            const F8 v0 = ldcg_f8(tblf + (size_t)r0 * D_DIM + sublane * 8);
            const F8 v1 = ldcg_f8(tblf + (size_t)r1 * D_DIM + sublane * 8);
            #pragma unroll
            for (int k = 0; k < 8; k++) acc[k] += v0.f[k];
            #pragma unroll
            for (int k = 0; k < 8; k++) acc[k] += v1.f[k];
        }

        // Combine halves: lane i (<16) += lane i+16 (same 32B slot, odd rows).
        #pragma unroll
        for (int k = 0; k < 8; k++)
            acc[k] += __shfl_down_sync(0xFFFFFFFFu, acc[k], 16);

        if (half == 0) {
            float* const orow = out + (size_t)b * (T_TABLES * D_DIM) + t * D_DIM
                                + sublane * 8;
            float4* const o4 = reinterpret_cast<float4*>(orow);
            o4[0] = make_float4(acc[0], acc[1], acc[2], acc[3]);
            o4[1] = make_float4(acc[4], acc[5], acc[6], acc[7]);
        }
    } else {
        // Generic ragged fallback (R3 path): lane owns float4 slot.
        const float4* __restrict__ tbl = reinterpret_cast<const float4*>(tblf);
        float4 a0 = make_float4(0.f, 0.f, 0.f, 0.f);
        float4 a1 = make_float4(0.f, 0.f, 0.f, 0.f);
        float4 a2 = make_float4(0.f, 0.f, 0.f, 0.f);
        float4 a3 = make_float4(0.f, 0.f, 0.f, 0.f);
        int j = start;
        const int n4 = start + (n & ~3);
        #pragma unroll 1
        for (; j < n4; j += 4) {
            const int i0 = indices[j + 0];
            const int i1 = indices[j + 1];
            const int i2 = indices[j + 2];
            const int i3 = indices[j + 3];
            acc_add(a0, ldcg_f4(tbl + (size_t)i0 * (D_DIM / 4) + lane));
            acc_add(a1, ldcg_f4(tbl + (size_t)i1 * (D_DIM / 4) + lane));
            acc_add(a2, ldcg_f4(tbl + (size_t)i2 * (D_DIM / 4) + lane));
            acc_add(a3, ldcg_f4(tbl + (size_t)i3 * (D_DIM / 4) + lane));
        }
        for (; j < end; j++) {
            const int i0 = indices[j];
            acc_add(a0, ldcg_f4(tbl + (size_t)i0 * (D_DIM / 4) + lane));
        }
        acc_add(a0, a1);
        acc_add(a2, a3);
        acc_add(a0, a2);
        float4* const o =
            reinterpret_cast<float4*>(out + (size_t)b * (T_TABLES * D_DIM) + t * D_DIM);
        o[lane] = a0;
    }
}

extern "C" void kernel_launch(void* const* d_in, const int* in_sizes, int n_in,
                              void* d_out, int out_size) {
    const float* weights = (const float*)d_in[0];
    const int*   indices = (const int*)d_in[1];
    const int*   offsets = (const int*)d_in[2];
    float*       out     = (float*)d_out;

    const int num_bags = T_TABLES * B_BAGS;           // 65536 warps
    const int threads  = 256;                          // 8 warps / block
    const int blocks   = (num_bags * 32 + threads - 1) / threads;  // 8192

    tbe_forward_kernel<<<blocks, threads>>>(weights, indices, offsets, out);
}

// round 11
// speedup vs baseline: 1.0600x; 1.0600x over previous
#include <cuda_runtime.h>
#include <stdint.h>

// TBE pooled embedding forward — FINAL kernel (empirical optimum, R3/R9).
// weights: [T, E, D] fp32; indices: [T*B*L] int32; offsets: [T*B+1] int32
// out: [B, T*D] fp32, pooled bag (t, b) -> out[b, t*D : (t+1)*D]
//
// One warp per bag; lane owns one float4 slot of the 512B row -> each row
// gather is a single coalesced LDG.128 warp transaction, .cg (L2-only).
//
// Findings locked in across R2-R10 (all ncu-verified):
//  - DRAM traffic is at the compulsory floor (~497 MB = ~56k unique rows x
//    16 tables x 512B + output + indices). L2 dedups all duplicate rows.
//  - ~6.0 TB/s (75% of spec) is the DRAM service ceiling for random 512B
//    granules + write mix: invariant across occ 54-88%, MLP 4-20, LDG.128
//    vs LDG.256, and all TMA variants (pure/hybrid/warp-specialized all
//    regress). Forcing 32 regs spills idx[]/v[] -> +70MB traffic, -17%.
//  - This configuration (40 regs, occ ~70%, MLP 20) = 82.4us, reproduced.

#define T_TABLES 16
#define E_ROWS   100000
#define D_DIM    128
#define B_BAGS   4096

__device__ __forceinline__ float4 ldcg_f4(const float4* p) {
    float4 v;
    asm volatile("ld.global.cg.v4.f32 {%0,%1,%2,%3}, [%4];"
                 : "=f"(v.x), "=f"(v.y), "=f"(v.z), "=f"(v.w) : "l"(p));
    return v;
}

__device__ __forceinline__ void acc_add(float4& a, const float4 v) {
    a.x += v.x; a.y += v.y; a.z += v.z; a.w += v.w;
}

__global__ __launch_bounds__(256, 6)
void tbe_forward_kernel(const float* __restrict__ weights,
                        const int* __restrict__ indices,
                        const int* __restrict__ offsets,
                        float* __restrict__ out) {
    const int warp_id = (blockIdx.x * blockDim.x + threadIdx.x) >> 5;
    const int lane    = threadIdx.x & 31;

    const int num_bags = T_TABLES * B_BAGS;
    if (warp_id >= num_bags) return;

    const int t = warp_id / B_BAGS;   // bags are table-major
    const int b = warp_id % B_BAGS;

    const int start = __ldg(offsets + warp_id);
    const int end   = __ldg(offsets + warp_id + 1);
    const int n     = end - start;

    const float4* __restrict__ tbl =
        reinterpret_cast<const float4*>(weights + (size_t)t * E_ROWS * D_DIM);

    float4 a0 = make_float4(0.f, 0.f, 0.f, 0.f);
    float4 a1 = make_float4(0.f, 0.f, 0.f, 0.f);
    float4 a2 = make_float4(0.f, 0.f, 0.f, 0.f);
    float4 a3 = make_float4(0.f, 0.f, 0.f, 0.f);

    if (n == 20 && ((start & 3) == 0)) {
        // Fast path: 5 vectorized index loads, then 20 independent row gathers.
        const int4* __restrict__ ip = reinterpret_cast<const int4*>(indices + start);
        int idx[20];
        #pragma unroll
        for (int g = 0; g < 5; g++) {
            const int4 q = ip[g];
            idx[g * 4 + 0] = q.x;
            idx[g * 4 + 1] = q.y;
            idx[g * 4 + 2] = q.z;
            idx[g * 4 + 3] = q.w;
        }
        float4 v[20];
        #pragma unroll
        for (int k = 0; k < 20; k++)
            v[k] = ldcg_f4(tbl + (size_t)idx[k] * (D_DIM / 4) + lane);
        #pragma unroll
        for (int k = 0; k < 20; k += 4) {
            acc_add(a0, v[k + 0]);
            acc_add(a1, v[k + 1]);
            acc_add(a2, v[k + 2]);
            acc_add(a3, v[k + 3]);
        }
    } else {
        // Generic ragged fallback.
        int j = start;
        const int n4 = start + (n & ~3);
        #pragma unroll 1
        for (; j < n4; j += 4) {
            const int i0 = indices[j + 0];
            const int i1 = indices[j + 1];
            const int i2 = indices[j + 2];
            const int i3 = indices[j + 3];
            acc_add(a0, ldcg_f4(tbl + (size_t)i0 * (D_DIM / 4) + lane));
            acc_add(a1, ldcg_f4(tbl + (size_t)i1 * (D_DIM / 4) + lane));
            acc_add(a2, ldcg_f4(tbl + (size_t)i2 * (D_DIM / 4) + lane));
            acc_add(a3, ldcg_f4(tbl + (size_t)i3 * (D_DIM / 4) + lane));
        }
        for (; j < end; j++) {
            const int i0 = indices[j];
            acc_add(a0, ldcg_f4(tbl + (size_t)i0 * (D_DIM / 4) + lane));
        }
    }

    acc_add(a0, a1);
    acc_add(a2, a3);
    acc_add(a0, a2);

    float4* const o =
        reinterpret_cast<float4*>(out + (size_t)b * (T_TABLES * D_DIM) + t * D_DIM);
    o[lane] = a0;
}

extern "C" void kernel_launch(void* const* d_in, const int* in_sizes, int n_in,
                              void* d_out, int out_size) {
    const float* weights = (const float*)d_in[0];
    const int*   indices = (const int*)d_in[1];
    const int*   offsets = (const int*)d_in[2];
    float*       out     = (float*)d_out;

    const int num_bags = T_TABLES * B_BAGS;           // 65536 warps
    const int threads  = 256;                          // 8 warps / block
    const int blocks   = (num_bags * 32 + threads - 1) / threads;  // 8192

    tbe_forward_kernel<<<blocks, threads>>>(weights, indices, offsets, out);
}

// round 12
// speedup vs baseline: 1.0633x; 1.0031x over previous
#include <cuda_runtime.h>
#include <stdint.h>

// TBE pooled embedding forward — FINAL kernel (converged optimum).
// weights: [T, E, D] fp32; indices: [T*B*L] int32; offsets: [T*B+1] int32
// out: [B, T*D] fp32, pooled bag (t, b) -> out[b, t*D : (t+1)*D]
//
// One warp per bag; lane owns one float4 slot of the 512B row -> each row
// gather is a single coalesced LDG.128 warp transaction, .cg (L2-only).
//
// Converged across 11 rounds (all ncu-verified):
//  - DRAM traffic measured at the compulsory floor (~496 MB = unique rows +
//    output + indices; L2 dedups all duplicate rows; table-major bag order
//    keeps each wave's unique-row window inside L2).
//  - ~6.0 TB/s (75% of spec) is the DRAM service ceiling for random 512B
//    granules + write mix: invariant across occ 54-88%, MLP 4-20, LDG.128
//    vs LDG.256, .cg/.cs, and all TMA variants (pure/hybrid/warp-specialized
//    all regress). Forcing 32 regs spills idx[]/v[] -> +70MB traffic, -17%.
//  - dur = floor/ceiling ~ 83us; this kernel hits it (82.4us, reproduced 3x).

#define T_TABLES 16
#define E_ROWS   100000
#define D_DIM    128
#define B_BAGS   4096

__device__ __forceinline__ float4 ldcg_f4(const float4* p) {
    float4 v;
    asm volatile("ld.global.cg.v4.f32 {%0,%1,%2,%3}, [%4];"
                 : "=f"(v.x), "=f"(v.y), "=f"(v.z), "=f"(v.w) : "l"(p));
    return v;
}

__device__ __forceinline__ void acc_add(float4& a, const float4 v) {
    a.x += v.x; a.y += v.y; a.z += v.z; a.w += v.w;
}

__global__ __launch_bounds__(256, 6)
void tbe_forward_kernel(const float* __restrict__ weights,
                        const int* __restrict__ indices,
                        const int* __restrict__ offsets,
                        float* __restrict__ out) {
    const int warp_id = (blockIdx.x * blockDim.x + threadIdx.x) >> 5;
    const int lane    = threadIdx.x & 31;

    const int num_bags = T_TABLES * B_BAGS;
    if (warp_id >= num_bags) return;

    const int t = warp_id / B_BAGS;   // bags are table-major
    const int b = warp_id % B_BAGS;

    const int start = __ldg(offsets + warp_id);
    const int end   = __ldg(offsets + warp_id + 1);
    const int n     = end - start;

    const float4* __restrict__ tbl =
        reinterpret_cast<const float4*>(weights + (size_t)t * E_ROWS * D_DIM);

    float4 a0 = make_float4(0.f, 0.f, 0.f, 0.f);
    float4 a1 = make_float4(0.f, 0.f, 0.f, 0.f);
    float4 a2 = make_float4(0.f, 0.f, 0.f, 0.f);
    float4 a3 = make_float4(0.f, 0.f, 0.f, 0.f);

    if (n == 20 && ((start & 3) == 0)) {
        // Fast path: 5 vectorized index loads, then 20 independent row gathers.
        const int4* __restrict__ ip = reinterpret_cast<const int4*>(indices + start);
        int idx[20];
        #pragma unroll
        for (int g = 0; g < 5; g++) {
            const int4 q = ip[g];
            idx[g * 4 + 0] = q.x;
            idx[g * 4 + 1] = q.y;
            idx[g * 4 + 2] = q.z;
            idx[g * 4 + 3] = q.w;
        }
        float4 v[20];
        #pragma unroll
        for (int k = 0; k < 20; k++)
            v[k] = ldcg_f4(tbl + (size_t)idx[k] * (D_DIM / 4) + lane);
        #pragma unroll
        for (int k = 0; k < 20; k += 4) {
            acc_add(a0, v[k + 0]);
            acc_add(a1, v[k + 1]);
            acc_add(a2, v[k + 2]);
            acc_add(a3, v[k + 3]);
        }
    } else {
        // Generic ragged fallback.
        int j = start;
        const int n4 = start + (n & ~3);
        #pragma unroll 1
        for (; j < n4; j += 4) {
            const int i0 = indices[j + 0];
            const int i1 = indices[j + 1];
            const int i2 = indices[j + 2];
            const int i3 = indices[j + 3];
            acc_add(a0, ldcg_f4(tbl + (size_t)i0 * (D_DIM / 4) + lane));
            acc_add(a1, ldcg_f4(tbl + (size_t)i1 * (D_DIM / 4) + lane));
            acc_add(a2, ldcg_f4(tbl + (size_t)i2 * (D_DIM / 4) + lane));
            acc_add(a3, ldcg_f4(tbl + (size_t)i3 * (D_DIM / 4) + lane));
        }
        for (; j < end; j++) {
            const int i0 = indices[j];
            acc_add(a0, ldcg_f4(tbl + (size_t)i0 * (D_DIM / 4) + lane));
        }
    }

    acc_add(a0, a1);
    acc_add(a2, a3);
    acc_add(a0, a2);

    float4* const o =
        reinterpret_cast<float4*>(out + (size_t)b * (T_TABLES * D_DIM) + t * D_DIM);
    o[lane] = a0;
}

extern "C" void kernel_launch(void* const* d_in, const int* in_sizes, int n_in,
                              void* d_out, int out_size) {
    const float* weights = (const float*)d_in[0];
    const int*   indices = (const int*)d_in[1];
    const int*   offsets = (const int*)d_in[2];
    float*       out     = (float*)d_out;

    const int num_bags = T_TABLES * B_BAGS;           // 65536 warps
    const int threads  = 256;                          // 8 warps / block
    const int blocks   = (num_bags * 32 + threads - 1) / threads;  // 8192

    tbe_forward_kernel<<<blocks, threads>>>(weights, indices, offsets, out);
}